// round 2
// baseline (speedup 1.0000x reference)
#include <cuda_runtime.h>
#include <cuda_bf16.h>

// Problem constants
#define BSZ   256
#define LSEQ  65536
#define HIST  256
#define WINW  64
#define DIMC  256
#define NPAT  64
#define TSTEP 1024            // (LSEQ + HIST-1 - HIST)/WINW + 1

#define TT    32              // t-tiles per block in kernel 1
#define XWIN  ((TT-1)*WINW + HIST)   // 2240 floats of x per block

// smem layout (floats) for kernel 1
#define OFF_SX     0
#define OFF_OUTS   (XWIN)                         // 2240
#define ROWP       (DIMC + 4)                     // 260, padded row
#define OFF_KEYST  (OFF_OUTS + TT*ROWP)           // 2240 + 8320 = 10560
#define SMEM_FLOATS (OFF_KEYST + NPAT*ROWP)       // 10560 + 16640 = 27200
#define SMEM_BYTES  (SMEM_FLOATS * 4)             // 108800 B

// Scratch: scores[b][t][p]  (B*T*P fp32 = 64 MiB)
__device__ float g_scores[BSZ * TSTEP * NPAT];

// ---------------------------------------------------------------------------
// Kernel 1: conv1d(stride 64, k=256, left pad 255) + bias + ReLU, then
//           scores = clip(out @ keys, 0, 6), written to g_scores[b][t][p].
// Block: 256 threads. blockIdx.x = b, blockIdx.y = t-tile.
// ---------------------------------------------------------------------------
__global__ __launch_bounds__(256, 2)
void conv_scores_kernel(const float* __restrict__ x,
                        const float* __restrict__ conv_w,
                        const float* __restrict__ conv_b,
                        const float* __restrict__ keys)
{
    extern __shared__ float smem[];
    float* sx     = smem + OFF_SX;      // [XWIN]
    float* souts  = smem + OFF_OUTS;    // [TT][ROWP]
    float* skeyst = smem + OFF_KEYST;   // [NPAT][ROWP]  (keys transposed)

    const int b   = blockIdx.x;
    const int t0  = blockIdx.y * TT;
    const int tid = threadIdx.x;        // == output channel d in conv phase

    // ---- load x window (zero-fill the left pad region) ----
    {
        const int base = t0 * WINW - (HIST - 1);
        const float* xr = x + (size_t)b * LSEQ;
        for (int i = tid; i < XWIN; i += 256) {
            int pos = base + i;
            sx[i] = (pos >= 0) ? xr[pos] : 0.0f;
        }
    }
    // ---- load keys transposed: skeyst[p][d] = keys[d][p] ----
    for (int i = tid; i < DIMC * NPAT; i += 256) {
        int d = i >> 6;
        int p = i & 63;
        skeyst[p * ROWP + d] = keys[i];
    }
    __syncthreads();

    // ---- conv: thread d accumulates 32 t outputs ----
    float acc[TT];
#pragma unroll
    for (int t = 0; t < TT; t++) acc[t] = 0.0f;

    const float* wrow = conv_w + (size_t)tid * HIST;   // w[d][*], contiguous
    for (int k0 = 0; k0 < HIST; k0 += 8) {
        const float4 wa = *reinterpret_cast<const float4*>(wrow + k0);
        const float4 wb = *reinterpret_cast<const float4*>(wrow + k0 + 4);
#pragma unroll
        for (int t = 0; t < TT; t++) {
            // window element k for output t lives at sx[t*WINW + k]
            const float4 xa = *reinterpret_cast<const float4*>(&sx[t * WINW + k0]);
            const float4 xb = *reinterpret_cast<const float4*>(&sx[t * WINW + k0 + 4]);
            float a = acc[t];
            a = fmaf(wa.x, xa.x, a);
            a = fmaf(wa.y, xa.y, a);
            a = fmaf(wa.z, xa.z, a);
            a = fmaf(wa.w, xa.w, a);
            a = fmaf(wb.x, xb.x, a);
            a = fmaf(wb.y, xb.y, a);
            a = fmaf(wb.z, xb.z, a);
            a = fmaf(wb.w, xb.w, a);
            acc[t] = a;
        }
    }

    // bias + ReLU -> smem out tile
    {
        const float bd = conv_b[tid];
#pragma unroll
        for (int t = 0; t < TT; t++) {
            souts[t * ROWP + tid] = fmaxf(acc[t] + bd, 0.0f);
        }
    }
    __syncthreads();

    // ---- scores: 32 t x 64 p = 2048 dot products of length 256 ----
    float* sc = g_scores + (((size_t)b * TSTEP + t0) * NPAT);
#pragma unroll
    for (int r = 0; r < 8; r++) {
        const int idx = r * 256 + tid;   // 0..2047
        const int t = idx >> 6;
        const int p = idx & 63;
        const float* orow = &souts[t * ROWP];
        const float* krow = &skeyst[p * ROWP];
        float s = 0.0f;
#pragma unroll 8
        for (int d = 0; d < DIMC; d += 4) {
            const float4 ov = *reinterpret_cast<const float4*>(orow + d);
            const float4 kv = *reinterpret_cast<const float4*>(krow + d);
            s = fmaf(ov.x, kv.x, s);
            s = fmaf(ov.y, kv.y, s);
            s = fmaf(ov.z, kv.z, s);
            s = fmaf(ov.w, kv.w, s);
        }
        s = fminf(fmaxf(s, 0.0f), 6.0f);           // relu6
        sc[t * NPAT + p] = s;
    }
}

// ---------------------------------------------------------------------------
// Kernel 2: sequential softmax-EMA scan over t, fused with
//           signal = probs @ shapes and out = relu(signal - x).
// One warp per batch row. Lane handles patterns {lane, lane+32} and output
// columns {lane, lane+32}. shapes kept fully in registers (128 floats/lane).
// ---------------------------------------------------------------------------
__global__ __launch_bounds__(32)
void scan_signal_kernel(const float* __restrict__ avg_scores,
                        const float* __restrict__ shapes,
                        const float* __restrict__ x,
                        float* __restrict__ out)
{
    const int b    = blockIdx.x;
    const int lane = threadIdx.x;

    __shared__ __align__(16) float prob_s[NPAT];

    // shapes[p][w] for all p at w = lane and w = lane+32 -> registers
    float sh0[NPAT], sh1[NPAT];
#pragma unroll
    for (int p = 0; p < NPAT; p++) {
        sh0[p] = shapes[p * WINW + lane];
        sh1[p] = shapes[p * WINW + lane + 32];
    }

    float avg0 = avg_scores[b * NPAT + lane];
    float avg1 = avg_scores[b * NPAT + lane + 32];

    const float* srow = g_scores + (size_t)b * TSTEP * NPAT;
    const float* xrow = x   + (size_t)b * LSEQ;
    float*       orow = out + (size_t)b * LSEQ;
    const float invP = 1.0f / (float)NPAT;

    for (int t = 0; t < TSTEP; t++) {
        const float s0 = srow[t * NPAT + lane];
        const float s1 = srow[t * NPAT + lane + 32];

        // softmax(score - avg) over 64 patterns; max-subtraction cancels
        // analytically and values stay in a small range (|s-avg| <~ 12).
        const float e0 = __expf(s0 - avg0);
        const float e1 = __expf(s1 - avg1);
        float sum = e0 + e1;
#pragma unroll
        for (int o = 16; o > 0; o >>= 1)
            sum += __shfl_xor_sync(0xFFFFFFFFu, sum, o);
        const float inv = __fdividef(1.0f, sum);
        const float p0 = e0 * inv;
        const float p1 = e1 * inv;

        avg0 += p0 - invP;
        avg1 += p1 - invP;

        prob_s[lane]      = p0;
        prob_s[lane + 32] = p1;
        __syncwarp();

        // signal[w] = sum_p prob[p] * shapes[p][w]
        float sig0 = 0.0f, sig1 = 0.0f;
#pragma unroll
        for (int p = 0; p < NPAT; p += 4) {
            const float4 pr = *reinterpret_cast<const float4*>(&prob_s[p]);
            sig0 = fmaf(pr.x, sh0[p + 0], sig0);
            sig0 = fmaf(pr.y, sh0[p + 1], sig0);
            sig0 = fmaf(pr.z, sh0[p + 2], sig0);
            sig0 = fmaf(pr.w, sh0[p + 3], sig0);
            sig1 = fmaf(pr.x, sh1[p + 0], sig1);
            sig1 = fmaf(pr.y, sh1[p + 1], sig1);
            sig1 = fmaf(pr.z, sh1[p + 2], sig1);
            sig1 = fmaf(pr.w, sh1[p + 3], sig1);
        }

        const int o0 = t * WINW + lane;
        const float x0 = xrow[o0];
        const float x1 = xrow[o0 + 32];
        orow[o0]      = fmaxf(sig0 - x0, 0.0f);
        orow[o0 + 32] = fmaxf(sig1 - x1, 0.0f);
        __syncwarp();   // protect prob_s before next iteration's writes
    }
}

// ---------------------------------------------------------------------------
extern "C" void kernel_launch(void* const* d_in, const int* in_sizes, int n_in,
                              void* d_out, int out_size)
{
    const float* x          = (const float*)d_in[0];  // (B, L)
    const float* avg_scores = (const float*)d_in[1];  // (B, NPAT)
    const float* conv_w     = (const float*)d_in[2];  // (DIM, 1, HIST)
    const float* conv_b     = (const float*)d_in[3];  // (DIM,)
    const float* keys       = (const float*)d_in[4];  // (DIM, NPAT)
    const float* shapes     = (const float*)d_in[5];  // (NPAT, WIN)
    float* out = (float*)d_out;                        // (B, L)

    cudaFuncSetAttribute(conv_scores_kernel,
                         cudaFuncAttributeMaxDynamicSharedMemorySize,
                         SMEM_BYTES);

    dim3 grid1(BSZ, TSTEP / TT);   // 256 x 32
    conv_scores_kernel<<<grid1, 256, SMEM_BYTES>>>(x, conv_w, conv_b, keys);

    scan_signal_kernel<<<BSZ, 32>>>(avg_scores, shapes, x, out);
}

// round 5
// speedup vs baseline: 2.1437x; 2.1437x over previous
#include <cuda_runtime.h>
#include <cuda_bf16.h>
#include <cstdint>

// Problem constants
#define BSZ   256
#define LSEQ  65536
#define HIST  256
#define WINW  64
#define DIMC  256
#define NPAT  64
#define TSTEP 1024

// Kernel-1 tiling
#define TT    64                 // t rows per block (4 m-tiles of 16)
#define ROWP  260                // padded row stride (floats) -> conflict-free frags

// smem layout (floats)
#define OFF_A    0                       // sA / sOut : 64 x 260
#define OFF_KHI  (64*ROWP)               // 16640
#define OFF_KLO  (OFF_KHI + 64*ROWP)     // 33280
#define OFF_BIAS (OFF_KLO + 64*ROWP)     // 49920
#define SMEM_FLOATS (OFF_BIAS + 256)     // 50176
#define SMEM_BYTES  (SMEM_FLOATS * 4)    // 200704

// Scratch: scores[b][t][p]  (64 MiB)
__device__ float g_scores[BSZ * TSTEP * NPAT];

// ---------------------------------------------------------------------------
__device__ __forceinline__ uint32_t f2tf32(float f) {
    uint32_t r;
    asm("cvt.rna.tf32.f32 %0, %1;" : "=r"(r) : "f"(f));
    return r;
}

// D += A(16x8, tf32, row) * B(8x8, tf32, col), fp32 accum
__device__ __forceinline__ void mma8(float c[4], const uint32_t a[4],
                                     uint32_t b0, uint32_t b1) {
    asm volatile(
        "mma.sync.aligned.m16n8k8.row.col.f32.tf32.tf32.f32 "
        "{%0,%1,%2,%3}, {%4,%5,%6,%7}, {%8,%9}, {%0,%1,%2,%3};\n"
        : "+f"(c[0]), "+f"(c[1]), "+f"(c[2]), "+f"(c[3])
        : "r"(a[0]), "r"(a[1]), "r"(a[2]), "r"(a[3]), "r"(b0), "r"(b1));
}

// ---------------------------------------------------------------------------
// Kernel 1: conv-as-GEMM (tf32 MMA) + relu + scores-GEMM + relu6.
// Block 256 threads (8 warps); blockIdx.x = b, blockIdx.y = t-tile (64 rows).
// Conv: warp w owns d-slice [32w, 32w+32), all 64 t. x split hi/lo (2 MMAs),
// W rounded once. Scores: warp w owns p-tile [8w, 8w+8); keys split hi/lo.
// ---------------------------------------------------------------------------
__global__ __launch_bounds__(256, 1)
void conv_scores_mma(const float* __restrict__ x,
                     const float* __restrict__ conv_w,
                     const float* __restrict__ conv_b,
                     const float* __restrict__ keys)
{
    extern __shared__ float sm[];
    float* sA    = sm + OFF_A;      // x windows, later conv output
    float* sKhi  = sm + OFF_KHI;    // keys hi, [p][d], stride ROWP
    float* sKlo  = sm + OFF_KLO;    // keys lo
    float* sBias = sm + OFF_BIAS;

    const int b    = blockIdx.x;
    const int t0   = blockIdx.y * TT;
    const int tid  = threadIdx.x;
    const int w    = tid >> 5;
    const int lane = tid & 31;
    const int gid  = lane >> 2;     // 0..7
    const int tig  = lane & 3;      // 0..3

    // ---- stage x windows into sA[t][k] (with left-pad zeros) ----
    {
        const float* xr = x + (size_t)b * LSEQ;
        const int base = t0 * WINW - (HIST - 1);
        for (int i = tid; i < TT * HIST; i += 256) {
            int t = i >> 8, k = i & 255;
            int pos = base + t * WINW + k;
            sA[t * ROWP + k] = (pos >= 0) ? xr[pos] : 0.0f;
        }
    }
    // ---- keys -> hi/lo transposed: sK[p][d] ----
    for (int i = tid; i < DIMC * NPAT; i += 256) {
        int d = i >> 6, p = i & 63;
        float v = keys[i];
        float hf = __uint_as_float(f2tf32(v));
        sKhi[p * ROWP + d] = hf;
        sKlo[p * ROWP + d] = v - hf;
    }
    sBias[tid] = conv_b[tid];
    __syncthreads();

    // ================= conv GEMM: C[64 x 32] per warp =================
    float acc[4][4][4] = {};            // [m-tile][n-tile][frag]
    const int n0w = w * 32;

    for (int kt = 0; kt < 32; kt++) {
        const int k0 = kt * 8;
        uint32_t ahi[4][4], alo[4][4];
#pragma unroll
        for (int mt = 0; mt < 4; mt++) {
            const float* pA = &sA[(mt * 16 + gid) * ROWP + k0 + tig];
            float a0 = pA[0];
            float a1 = pA[8 * ROWP];
            float a2 = pA[4];
            float a3 = pA[8 * ROWP + 4];
            ahi[mt][0] = f2tf32(a0); alo[mt][0] = __float_as_uint(a0 - __uint_as_float(ahi[mt][0]));
            ahi[mt][1] = f2tf32(a1); alo[mt][1] = __float_as_uint(a1 - __uint_as_float(ahi[mt][1]));
            ahi[mt][2] = f2tf32(a2); alo[mt][2] = __float_as_uint(a2 - __uint_as_float(ahi[mt][2]));
            ahi[mt][3] = f2tf32(a3); alo[mt][3] = __float_as_uint(a3 - __uint_as_float(ahi[mt][3]));
        }
#pragma unroll
        for (int nt = 0; nt < 4; nt++) {
            const float* pW = conv_w + (size_t)(n0w + nt * 8 + gid) * HIST + k0 + tig;
            uint32_t b0 = f2tf32(pW[0]);
            uint32_t b1 = f2tf32(pW[4]);
#pragma unroll
            for (int mt = 0; mt < 4; mt++) {
                mma8(acc[mt][nt], ahi[mt], b0, b1);
                mma8(acc[mt][nt], alo[mt], b0, b1);
            }
        }
    }
    __syncthreads();   // all warps done reading sA

    // ---- epilogue: bias + relu -> sOut (overwrites sA) ----
#pragma unroll
    for (int mt = 0; mt < 4; mt++) {
#pragma unroll
        for (int nt = 0; nt < 4; nt++) {
            const int col = n0w + nt * 8 + 2 * tig;
            const float bb0 = sBias[col], bb1 = sBias[col + 1];
            const int r0 = mt * 16 + gid;
            float2 v0 = make_float2(fmaxf(acc[mt][nt][0] + bb0, 0.0f),
                                    fmaxf(acc[mt][nt][1] + bb1, 0.0f));
            float2 v1 = make_float2(fmaxf(acc[mt][nt][2] + bb0, 0.0f),
                                    fmaxf(acc[mt][nt][3] + bb1, 0.0f));
            *reinterpret_cast<float2*>(&sA[r0 * ROWP + col])       = v0;
            *reinterpret_cast<float2*>(&sA[(r0 + 8) * ROWP + col]) = v1;
        }
    }
    __syncthreads();

    // ================= scores GEMM: [64 x 8] per warp =================
    float sc[4][4] = {};
    const int p0 = w * 8;
    for (int kt = 0; kt < 32; kt++) {
        const int k0 = kt * 8;
        uint32_t af[4][4];
#pragma unroll
        for (int mt = 0; mt < 4; mt++) {
            const float* pA = &sA[(mt * 16 + gid) * ROWP + k0 + tig];
            af[mt][0] = f2tf32(pA[0]);
            af[mt][1] = f2tf32(pA[8 * ROWP]);
            af[mt][2] = f2tf32(pA[4]);
            af[mt][3] = f2tf32(pA[8 * ROWP + 4]);
        }
        const float* pKh = &sKhi[(p0 + gid) * ROWP + k0 + tig];
        const float* pKl = &sKlo[(p0 + gid) * ROWP + k0 + tig];
        uint32_t bh0 = __float_as_uint(pKh[0]);
        uint32_t bh1 = __float_as_uint(pKh[4]);
        uint32_t bl0 = __float_as_uint(pKl[0]);
        uint32_t bl1 = __float_as_uint(pKl[4]);
#pragma unroll
        for (int mt = 0; mt < 4; mt++) {
            mma8(sc[mt], af[mt], bh0, bh1);
            mma8(sc[mt], af[mt], bl0, bl1);
        }
    }

    // ---- epilogue: relu6 -> g_scores[b][t][p] ----
    {
        float* gs = g_scores + ((size_t)b * TSTEP + t0) * NPAT;
        const int p = p0 + 2 * tig;
#pragma unroll
        for (int mt = 0; mt < 4; mt++) {
            const int r0 = mt * 16 + gid;
            float2 u0 = make_float2(fminf(fmaxf(sc[mt][0], 0.0f), 6.0f),
                                    fminf(fmaxf(sc[mt][1], 0.0f), 6.0f));
            float2 u1 = make_float2(fminf(fmaxf(sc[mt][2], 0.0f), 6.0f),
                                    fminf(fmaxf(sc[mt][3], 0.0f), 6.0f));
            *reinterpret_cast<float2*>(&gs[r0 * NPAT + p])       = u0;
            *reinterpret_cast<float2*>(&gs[(r0 + 8) * NPAT + p]) = u1;
        }
    }
}

// ---------------------------------------------------------------------------
// Kernel 2: softmax-EMA scan fused with signal GEMV and output.
// One warp per batch. Depth-2 register prefetch of scores/x; GEMV on
// UNNORMALIZED e (scaled by 1/sum at the end) with packed f32x2 FMAs so it
// overlaps the shfl-reduce critical path.
// ---------------------------------------------------------------------------
__global__ __launch_bounds__(32)
void scan_signal_kernel(const float* __restrict__ avg_scores,
                        const float* __restrict__ shapes,
                        const float* __restrict__ x,
                        float* __restrict__ out)
{
    const int b    = blockIdx.x;
    const int lane = threadIdx.x;

    __shared__ __align__(16) float e_s[NPAT];

    // shapes packed in pattern-pairs: shp0[i] = (sh[2i][lane], sh[2i+1][lane])
    uint64_t shp0[NPAT / 2], shp1[NPAT / 2];
#pragma unroll
    for (int i = 0; i < NPAT / 2; i++) {
        float a0 = shapes[(2 * i) * WINW + lane];
        float a1 = shapes[(2 * i + 1) * WINW + lane];
        asm("mov.b64 %0, {%1, %2};" : "=l"(shp0[i]) : "f"(a0), "f"(a1));
        float c0 = shapes[(2 * i) * WINW + lane + 32];
        float c1 = shapes[(2 * i + 1) * WINW + lane + 32];
        asm("mov.b64 %0, {%1, %2};" : "=l"(shp1[i]) : "f"(c0), "f"(c1));
    }

    float avg0 = avg_scores[b * NPAT + lane];
    float avg1 = avg_scores[b * NPAT + lane + 32];

    const float* srow = g_scores + (size_t)b * TSTEP * NPAT;
    const float* xrow = x   + (size_t)b * LSEQ;
    float*       orow = out + (size_t)b * LSEQ;
    const float invP = 1.0f / (float)NPAT;

    // depth-2 prefetch pipeline
    float cs0 = srow[lane],       cs1 = srow[lane + 32];
    float ns0 = srow[64 + lane],  ns1 = srow[64 + lane + 32];
    float cx0 = xrow[lane],       cx1 = xrow[lane + 32];
    float nx0 = xrow[64 + lane],  nx1 = xrow[64 + lane + 32];

    for (int t = 0; t < TSTEP; t++) {
        const float s0 = cs0, s1 = cs1, xa = cx0, xb = cx1;
        cs0 = ns0; cs1 = ns1; cx0 = nx0; cx1 = nx1;
        if (t + 2 < TSTEP) {
            const float* sp = srow + (t + 2) * NPAT;
            ns0 = sp[lane]; ns1 = sp[lane + 32];
            const float* xp = xrow + (t + 2) * WINW;
            nx0 = xp[lane]; nx1 = xp[lane + 32];
        }

        const float e0 = __expf(s0 - avg0);
        const float e1 = __expf(s1 - avg1);
        e_s[lane]      = e0;
        e_s[lane + 32] = e1;
        __syncwarp();

        float sum = e0 + e1;
#pragma unroll
        for (int o = 16; o > 0; o >>= 1)
            sum += __shfl_xor_sync(0xFFFFFFFFu, sum, o);

        // GEMV on unnormalized e (independent of reduction -> overlaps it)
        uint64_t acc0 = 0ull, acc1 = 0ull;
        const uint64_t* ep = reinterpret_cast<const uint64_t*>(e_s);
#pragma unroll
        for (int i = 0; i < NPAT / 2; i++) {
            const uint64_t ev = ep[i];
            asm("fma.rn.f32x2 %0, %1, %2, %0;" : "+l"(acc0) : "l"(ev), "l"(shp0[i]));
            asm("fma.rn.f32x2 %0, %1, %2, %0;" : "+l"(acc1) : "l"(ev), "l"(shp1[i]));
        }

        const float inv = __fdividef(1.0f, sum);
        avg0 += fmaf(e0, inv, -invP);
        avg1 += fmaf(e1, inv, -invP);

        float l0, h0, l1, h1;
        asm("mov.b64 {%0, %1}, %2;" : "=f"(l0), "=f"(h0) : "l"(acc0));
        asm("mov.b64 {%0, %1}, %2;" : "=f"(l1), "=f"(h1) : "l"(acc1));
        const float sig0 = (l0 + h0) * inv;
        const float sig1 = (l1 + h1) * inv;

        const int o0 = t * WINW + lane;
        orow[o0]      = fmaxf(sig0 - xa, 0.0f);
        orow[o0 + 32] = fmaxf(sig1 - xb, 0.0f);
        __syncwarp();
    }
}

// ---------------------------------------------------------------------------
extern "C" void kernel_launch(void* const* d_in, const int* in_sizes, int n_in,
                              void* d_out, int out_size)
{
    const float* x          = (const float*)d_in[0];
    const float* avg_scores = (const float*)d_in[1];
    const float* conv_w     = (const float*)d_in[2];
    const float* conv_b     = (const float*)d_in[3];
    const float* keys       = (const float*)d_in[4];
    const float* shapes     = (const float*)d_in[5];
    float* out = (float*)d_out;

    cudaFuncSetAttribute(conv_scores_mma,
                         cudaFuncAttributeMaxDynamicSharedMemorySize,
                         SMEM_BYTES);

    dim3 grid1(BSZ, TSTEP / TT);   // 256 x 16
    conv_scores_mma<<<grid1, 256, SMEM_BYTES>>>(x, conv_w, conv_b, keys);

    scan_signal_kernel<<<BSZ, 32>>>(avg_scores, shapes, x, out);
}

// round 6
// speedup vs baseline: 3.2466x; 1.5144x over previous
#include <cuda_runtime.h>
#include <cuda_bf16.h>
#include <cstdint>

// Problem constants
#define BSZ   256
#define LSEQ  65536
#define HIST  256
#define WINW  64
#define DIMC  256
#define NPAT  64
#define TSTEP 1024

// Kernel-1 tiling
#define TT    64                 // t rows per block (4 m-tiles of 16)
#define ROWP  260                // padded row stride (floats) -> conflict-free frags

// smem layout (floats) for kernel 1
#define OFF_A    0                       // sA / sOut : 64 x 260
#define OFF_KEYS (64*ROWP)               // 16640
#define OFF_BIAS (OFF_KEYS + 64*ROWP)    // 33280
#define SMEM_FLOATS (OFF_BIAS + 256)     // 33536
#define SMEM_BYTES  (SMEM_FLOATS * 4)    // 134144 B

// Kernel-2 chunking
#define CCH   64
#define NCH   (TSTEP / CCH)              // 16

// Scratch: scores[b][t][p]  (64 MiB)
__device__ float g_scores[BSZ * TSTEP * NPAT];

// ---------------------------------------------------------------------------
__device__ __forceinline__ uint32_t f2tf32(float f) {
    uint32_t r;
    asm("cvt.rna.tf32.f32 %0, %1;" : "=r"(r) : "f"(f));
    return r;
}

// D += A(16x8, tf32, row) * B(8x8, tf32, col), fp32 accum
__device__ __forceinline__ void mma8(float c[4], const uint32_t a[4],
                                     uint32_t b0, uint32_t b1) {
    asm volatile(
        "mma.sync.aligned.m16n8k8.row.col.f32.tf32.tf32.f32 "
        "{%0,%1,%2,%3}, {%4,%5,%6,%7}, {%8,%9}, {%0,%1,%2,%3};\n"
        : "+f"(c[0]), "+f"(c[1]), "+f"(c[2]), "+f"(c[3])
        : "r"(a[0]), "r"(a[1]), "r"(a[2]), "r"(a[3]), "r"(b0), "r"(b1));
}

// ---------------------------------------------------------------------------
// Kernel 1: conv-as-GEMM (tf32 MMA, hi-only x) + relu + scores-GEMM + relu6.
// ---------------------------------------------------------------------------
__global__ __launch_bounds__(256, 1)
void conv_scores_mma(const float* __restrict__ x,
                     const float* __restrict__ conv_w,
                     const float* __restrict__ conv_b,
                     const float* __restrict__ keys)
{
    extern __shared__ float sm[];
    float* sA    = sm + OFF_A;      // x windows, later conv output
    float* sKey  = sm + OFF_KEYS;   // keys (tf32-rounded), [p][d], stride ROWP
    float* sBias = sm + OFF_BIAS;

    const int b    = blockIdx.x;
    const int t0   = blockIdx.y * TT;
    const int tid  = threadIdx.x;
    const int w    = tid >> 5;
    const int lane = tid & 31;
    const int gid  = lane >> 2;     // 0..7
    const int tig  = lane & 3;      // 0..3

    // ---- stage x windows into sA[t][k] (with left-pad zeros) ----
    {
        const float* xr = x + (size_t)b * LSEQ;
        const int base = t0 * WINW - (HIST - 1);
        for (int i = tid; i < TT * HIST; i += 256) {
            int t = i >> 8, k = i & 255;
            int pos = base + t * WINW + k;
            sA[t * ROWP + k] = (pos >= 0) ? xr[pos] : 0.0f;
        }
    }
    // ---- keys transposed + tf32-rounded: sKey[p][d] ----
    for (int i = tid; i < DIMC * NPAT; i += 256) {
        int d = i >> 6, p = i & 63;
        sKey[p * ROWP + d] = __uint_as_float(f2tf32(keys[i]));
    }
    sBias[tid] = conv_b[tid];
    __syncthreads();

    // ================= conv GEMM: C[64 x 32] per warp =================
    float acc[4][4][4] = {};            // [m-tile][n-tile][frag]
    const int n0w = w * 32;

    for (int kt = 0; kt < 32; kt++) {
        const int k0 = kt * 8;
        uint32_t ahi[4][4];
#pragma unroll
        for (int mt = 0; mt < 4; mt++) {
            const float* pA = &sA[(mt * 16 + gid) * ROWP + k0 + tig];
            ahi[mt][0] = f2tf32(pA[0]);
            ahi[mt][1] = f2tf32(pA[8 * ROWP]);
            ahi[mt][2] = f2tf32(pA[4]);
            ahi[mt][3] = f2tf32(pA[8 * ROWP + 4]);
        }
#pragma unroll
        for (int nt = 0; nt < 4; nt++) {
            const float* pW = conv_w + (size_t)(n0w + nt * 8 + gid) * HIST + k0 + tig;
            uint32_t b0 = f2tf32(pW[0]);
            uint32_t b1 = f2tf32(pW[4]);
#pragma unroll
            for (int mt = 0; mt < 4; mt++) {
                mma8(acc[mt][nt], ahi[mt], b0, b1);
            }
        }
    }
    __syncthreads();   // all warps done reading sA

    // ---- epilogue: bias + relu -> sOut (overwrites sA) ----
#pragma unroll
    for (int mt = 0; mt < 4; mt++) {
#pragma unroll
        for (int nt = 0; nt < 4; nt++) {
            const int col = n0w + nt * 8 + 2 * tig;
            const float bb0 = sBias[col], bb1 = sBias[col + 1];
            const int r0 = mt * 16 + gid;
            float2 v0 = make_float2(fmaxf(acc[mt][nt][0] + bb0, 0.0f),
                                    fmaxf(acc[mt][nt][1] + bb1, 0.0f));
            float2 v1 = make_float2(fmaxf(acc[mt][nt][2] + bb0, 0.0f),
                                    fmaxf(acc[mt][nt][3] + bb1, 0.0f));
            *reinterpret_cast<float2*>(&sA[r0 * ROWP + col])       = v0;
            *reinterpret_cast<float2*>(&sA[(r0 + 8) * ROWP + col]) = v1;
        }
    }
    __syncthreads();

    // ================= scores GEMM: [64 x 8] per warp =================
    float sc[4][4] = {};
    const int p0 = w * 8;
    for (int kt = 0; kt < 32; kt++) {
        const int k0 = kt * 8;
        uint32_t af[4][4];
#pragma unroll
        for (int mt = 0; mt < 4; mt++) {
            const float* pA = &sA[(mt * 16 + gid) * ROWP + k0 + tig];
            af[mt][0] = f2tf32(pA[0]);
            af[mt][1] = f2tf32(pA[8 * ROWP]);
            af[mt][2] = f2tf32(pA[4]);
            af[mt][3] = f2tf32(pA[8 * ROWP + 4]);
        }
        const float* pK = &sKey[(p0 + gid) * ROWP + k0 + tig];
        uint32_t bh0 = __float_as_uint(pK[0]);
        uint32_t bh1 = __float_as_uint(pK[4]);
#pragma unroll
        for (int mt = 0; mt < 4; mt++) {
            mma8(sc[mt], af[mt], bh0, bh1);
        }
    }

    // ---- epilogue: relu6 -> g_scores[b][t][p] ----
    {
        float* gs = g_scores + ((size_t)b * TSTEP + t0) * NPAT;
        const int p = p0 + 2 * tig;
#pragma unroll
        for (int mt = 0; mt < 4; mt++) {
            const int r0 = mt * 16 + gid;
            float2 u0 = make_float2(fminf(fmaxf(sc[mt][0], 0.0f), 6.0f),
                                    fminf(fmaxf(sc[mt][1], 0.0f), 6.0f));
            float2 u1 = make_float2(fminf(fmaxf(sc[mt][2], 0.0f), 6.0f),
                                    fminf(fmaxf(sc[mt][3], 0.0f), 6.0f));
            *reinterpret_cast<float2*>(&gs[r0 * NPAT + p])       = u0;
            *reinterpret_cast<float2*>(&gs[(r0 + 8) * NPAT + p]) = u1;
        }
    }
}

// ---------------------------------------------------------------------------
// Kernel 2: producer/consumer split.
// Block = 128 threads per batch. Warp 0 runs ONLY the softmax-EMA recurrence
// (deep register prefetch of scores, depth 8) and writes unnormalized e plus
// 1/sum into a double-buffered smem ring. Warps 1-3 consume chunk c-1:
// stage x to smem, GEMV (packed f32x2), write relu(sig - x).
// ---------------------------------------------------------------------------
__global__ __launch_bounds__(128)
void scan_signal_kernel(const float* __restrict__ avg_scores,
                        const float* __restrict__ shapes,
                        const float* __restrict__ x,
                        float* __restrict__ out)
{
    const int b    = blockIdx.x;
    const int tid  = threadIdx.x;
    const int w    = tid >> 5;
    const int lane = tid & 31;

    __shared__ __align__(16) float ring[2][CCH][NPAT];   // 32 KB
    __shared__ float s_inv[2][CCH];                      // 512 B
    __shared__ __align__(16) float s_x[CCH * WINW];      // 16 KB

    const float* srow = g_scores + (size_t)b * TSTEP * NPAT;
    const float* xrow = x   + (size_t)b * LSEQ;
    float*       orow = out + (size_t)b * LSEQ;
    const float invP = 1.0f / (float)NPAT;

    // ---- consumer-only: shapes in registers, packed pattern pairs ----
    uint64_t shp0[NPAT / 2], shp1[NPAT / 2];
    if (w > 0) {
#pragma unroll
        for (int i = 0; i < NPAT / 2; i++) {
            float a0 = shapes[(2 * i) * WINW + lane];
            float a1 = shapes[(2 * i + 1) * WINW + lane];
            asm("mov.b64 %0, {%1, %2};" : "=l"(shp0[i]) : "f"(a0), "f"(a1));
            float c0 = shapes[(2 * i) * WINW + lane + 32];
            float c1 = shapes[(2 * i + 1) * WINW + lane + 32];
            asm("mov.b64 %0, {%1, %2};" : "=l"(shp1[i]) : "f"(c0), "f"(c1));
        }
    }

    // ---- producer-only state ----
    float avg0 = 0.0f, avg1 = 0.0f;
    float pf0[8], pf1[8];
    if (w == 0) {
        avg0 = avg_scores[b * NPAT + lane];
        avg1 = avg_scores[b * NPAT + lane + 32];
#pragma unroll
        for (int j = 0; j < 8; j++) {
            pf0[j] = srow[j * NPAT + lane];
            pf1[j] = srow[j * NPAT + lane + 32];
        }
    }

    for (int c = 0; c <= NCH; c++) {
        if (w == 0) {
            if (c < NCH) {
                float* buf = &ring[c & 1][0][0];
                float* biv = s_inv[c & 1];
#pragma unroll 1
                for (int u = 0; u < CCH; u += 8) {
#pragma unroll
                    for (int j = 0; j < 8; j++) {
                        const int tt = u + j;
                        const int t  = c * CCH + tt;
                        const float s0 = pf0[j];
                        const float s1 = pf1[j];
                        const int tn = t + 8;
                        if (tn < TSTEP) {
                            pf0[j] = srow[tn * NPAT + lane];
                            pf1[j] = srow[tn * NPAT + lane + 32];
                        }
                        const float e0 = __expf(s0 - avg0);
                        const float e1 = __expf(s1 - avg1);
                        buf[tt * NPAT + lane]      = e0;
                        buf[tt * NPAT + lane + 32] = e1;
                        float sum = e0 + e1;
#pragma unroll
                        for (int o = 16; o > 0; o >>= 1)
                            sum += __shfl_xor_sync(0xFFFFFFFFu, sum, o);
                        const float inv = __fdividef(1.0f, sum);
                        if (lane == 0) biv[tt] = inv;
                        avg0 += fmaf(e0, inv, -invP);
                        avg1 += fmaf(e1, inv, -invP);
                    }
                }
            }
        } else {
            if (c > 0) {
                const int cc = c - 1;
                const float* buf = &ring[cc & 1][0][0];
                const float* biv = s_inv[cc & 1];

                // stage this chunk's x into smem (96 threads, float4)
                const float4* xc = reinterpret_cast<const float4*>(
                                       xrow + (size_t)cc * CCH * WINW);
                float4* sx4 = reinterpret_cast<float4*>(s_x);
                for (int i = tid - 32; i < CCH * WINW / 4; i += 96)
                    sx4[i] = xc[i];
                asm volatile("bar.sync 1, 96;" ::: "memory");

                for (int tt = w - 1; tt < CCH; tt += 3) {
                    const uint64_t* ep =
                        reinterpret_cast<const uint64_t*>(buf + tt * NPAT);
                    const float inv = biv[tt];
                    uint64_t acc0 = 0ull, acc1 = 0ull;
#pragma unroll
                    for (int i = 0; i < NPAT / 2; i++) {
                        const uint64_t ev = ep[i];
                        asm("fma.rn.f32x2 %0, %1, %2, %0;"
                            : "+l"(acc0) : "l"(ev), "l"(shp0[i]));
                        asm("fma.rn.f32x2 %0, %1, %2, %0;"
                            : "+l"(acc1) : "l"(ev), "l"(shp1[i]));
                    }
                    float l0, h0, l1, h1;
                    asm("mov.b64 {%0, %1}, %2;" : "=f"(l0), "=f"(h0) : "l"(acc0));
                    asm("mov.b64 {%0, %1}, %2;" : "=f"(l1), "=f"(h1) : "l"(acc1));
                    const float sig0 = (l0 + h0) * inv;
                    const float sig1 = (l1 + h1) * inv;

                    const float xa = s_x[tt * WINW + lane];
                    const float xb = s_x[tt * WINW + lane + 32];
                    const int o0 = (cc * CCH + tt) * WINW + lane;
                    orow[o0]      = fmaxf(sig0 - xa, 0.0f);
                    orow[o0 + 32] = fmaxf(sig1 - xb, 0.0f);
                }
            }
        }
        __syncthreads();
    }
}

// ---------------------------------------------------------------------------
extern "C" void kernel_launch(void* const* d_in, const int* in_sizes, int n_in,
                              void* d_out, int out_size)
{
    const float* x          = (const float*)d_in[0];
    const float* avg_scores = (const float*)d_in[1];
    const float* conv_w     = (const float*)d_in[2];
    const float* conv_b     = (const float*)d_in[3];
    const float* keys       = (const float*)d_in[4];
    const float* shapes     = (const float*)d_in[5];
    float* out = (float*)d_out;

    cudaFuncSetAttribute(conv_scores_mma,
                         cudaFuncAttributeMaxDynamicSharedMemorySize,
                         SMEM_BYTES);

    dim3 grid1(BSZ, TSTEP / TT);   // 256 x 16
    conv_scores_mma<<<grid1, 256, SMEM_BYTES>>>(x, conv_w, conv_b, keys);

    scan_signal_kernel<<<BSZ, 128>>>(avg_scores, shapes, x, out);
}

// round 8
// speedup vs baseline: 3.2709x; 1.0075x over previous
#include <cuda_runtime.h>
#include <cuda_bf16.h>
#include <cstdint>

// Problem constants
#define BSZ   256
#define LSEQ  65536
#define HIST  256
#define WINW  64
#define DIMC  256
#define NPAT  64
#define TSTEP 1024

// Kernel-1 tiling
#define TT    64                 // t rows per block (4 m-tiles of 16)
#define ROWP  260                // padded row stride (floats)

// smem layout (floats) for kernel 1
#define OFF_A    0                       // sA / sOut : 64 x 260
#define OFF_KEYS (64*ROWP)               // 16640
#define OFF_BIAS (OFF_KEYS + 64*ROWP)    // 33280
#define SMEM_FLOATS (OFF_BIAS + 256)     // 33536
#define SMEM_BYTES  (SMEM_FLOATS * 4)    // 134144 B

// Kernel-2 chunking
#define CCH   64
#define NCH   (TSTEP / CCH)              // 16

// Scratch: scores[b][t][p]  (64 MiB)
__device__ float g_scores[BSZ * TSTEP * NPAT];

// ---------------------------------------------------------------------------
__device__ __forceinline__ uint32_t f2tf32(float f) {
    uint32_t r;
    asm("cvt.rna.tf32.f32 %0, %1;" : "=r"(r) : "f"(f));
    return r;
}

// D += A(16x8, tf32, row) * B(8x8, tf32, col), fp32 accum
__device__ __forceinline__ void mma8(float c[4], const uint32_t a[4],
                                     uint32_t b0, uint32_t b1) {
    asm volatile(
        "mma.sync.aligned.m16n8k8.row.col.f32.tf32.tf32.f32 "
        "{%0,%1,%2,%3}, {%4,%5,%6,%7}, {%8,%9}, {%0,%1,%2,%3};\n"
        : "+f"(c[0]), "+f"(c[1]), "+f"(c[2]), "+f"(c[3])
        : "r"(a[0]), "r"(a[1]), "r"(a[2]), "r"(a[3]), "r"(b0), "r"(b1));
}

// ---------------------------------------------------------------------------
// Kernel 1: conv-as-GEMM (tf32 MMA) + relu + scores-GEMM + relu6.
// Hot loops fully software-pipelined: W (global) and A (smem) fragments are
// double-buffered one kt ahead; all tf32 rounding hoisted out of the loops.
// ---------------------------------------------------------------------------
__global__ __launch_bounds__(256, 1)
void conv_scores_mma(const float* __restrict__ x,
                     const float* __restrict__ conv_w,
                     const float* __restrict__ conv_b,
                     const float* __restrict__ keys)
{
    extern __shared__ float sm[];
    float* sA    = sm + OFF_A;      // x windows (tf32-rounded), later conv out
    float* sKey  = sm + OFF_KEYS;   // keys (tf32-rounded), [p][d]
    float* sBias = sm + OFF_BIAS;

    const int b    = blockIdx.x;
    const int t0   = blockIdx.y * TT;
    const int tid  = threadIdx.x;
    const int w    = tid >> 5;
    const int lane = tid & 31;
    const int gid  = lane >> 2;     // 0..7
    const int tig  = lane & 3;      // 0..3

    // ---- stage x windows, tf32-rounded, zero left pad ----
    {
        const float* xr = x + (size_t)b * LSEQ;
        const int base = t0 * WINW - (HIST - 1);
        for (int i = tid; i < TT * HIST; i += 256) {
            int t = i >> 8, k = i & 255;
            int pos = base + t * WINW + k;
            float v = (pos >= 0) ? xr[pos] : 0.0f;
            sA[t * ROWP + k] = __uint_as_float(f2tf32(v));
        }
    }
    // ---- keys transposed + tf32-rounded: sKey[p][d] ----
    for (int i = tid; i < DIMC * NPAT; i += 256) {
        int d = i >> 6, p = i & 63;
        sKey[p * ROWP + d] = __uint_as_float(f2tf32(keys[i]));
    }
    sBias[tid] = conv_b[tid];
    __syncthreads();

    // ================= conv GEMM: C[64 x 32] per warp =================
    float acc[4][4][4] = {};            // [m-tile][n-tile][frag]
    const int n0w = w * 32;

    // per-nt W row pointers (advance by 8 each kt)
    const float* pW[4];
#pragma unroll
    for (int nt = 0; nt < 4; nt++)
        pW[nt] = conv_w + (size_t)(n0w + nt * 8 + gid) * HIST + tig;

    uint32_t aw[2][4][4];   // A frags (already tf32 bits)
    float    wr[2][4][2];   // W raw fp32 (cvt at consume time)

    // prologue: kt = 0
#pragma unroll
    for (int mt = 0; mt < 4; mt++) {
        const float* pA = &sA[(mt * 16 + gid) * ROWP + tig];
        aw[0][mt][0] = __float_as_uint(pA[0]);
        aw[0][mt][1] = __float_as_uint(pA[8 * ROWP]);
        aw[0][mt][2] = __float_as_uint(pA[4]);
        aw[0][mt][3] = __float_as_uint(pA[8 * ROWP + 4]);
    }
#pragma unroll
    for (int nt = 0; nt < 4; nt++) {
        wr[0][nt][0] = pW[nt][0];
        wr[0][nt][1] = pW[nt][4];
    }

#pragma unroll 4
    for (int kt = 0; kt < 32; kt++) {
        const int cur = kt & 1, nxt = cur ^ 1;
        // issue next-kt loads first (latency hidden behind this kt's MMAs)
        if (kt < 31) {
            const int k1 = (kt + 1) * 8;
#pragma unroll
            for (int nt = 0; nt < 4; nt++) {
                wr[nxt][nt][0] = pW[nt][k1];
                wr[nxt][nt][1] = pW[nt][k1 + 4];
            }
#pragma unroll
            for (int mt = 0; mt < 4; mt++) {
                const float* pA = &sA[(mt * 16 + gid) * ROWP + k1 + tig];
                aw[nxt][mt][0] = __float_as_uint(pA[0]);
                aw[nxt][mt][1] = __float_as_uint(pA[8 * ROWP]);
                aw[nxt][mt][2] = __float_as_uint(pA[4]);
                aw[nxt][mt][3] = __float_as_uint(pA[8 * ROWP + 4]);
            }
        }
        // cvt current W (loaded last iteration -> ready), then MMAs
#pragma unroll
        for (int nt = 0; nt < 4; nt++) {
            const uint32_t b0 = f2tf32(wr[cur][nt][0]);
            const uint32_t b1 = f2tf32(wr[cur][nt][1]);
#pragma unroll
            for (int mt = 0; mt < 4; mt++)
                mma8(acc[mt][nt], aw[cur][mt], b0, b1);
        }
    }
    __syncthreads();   // all warps done reading sA (x windows)

    // ---- epilogue: bias + relu, tf32-round, -> sOut (overwrites sA) ----
#pragma unroll
    for (int mt = 0; mt < 4; mt++) {
#pragma unroll
        for (int nt = 0; nt < 4; nt++) {
            const int col = n0w + nt * 8 + 2 * tig;
            const float bb0 = sBias[col], bb1 = sBias[col + 1];
            const int r0 = mt * 16 + gid;
            float2 v0, v1;
            v0.x = __uint_as_float(f2tf32(fmaxf(acc[mt][nt][0] + bb0, 0.0f)));
            v0.y = __uint_as_float(f2tf32(fmaxf(acc[mt][nt][1] + bb1, 0.0f)));
            v1.x = __uint_as_float(f2tf32(fmaxf(acc[mt][nt][2] + bb0, 0.0f)));
            v1.y = __uint_as_float(f2tf32(fmaxf(acc[mt][nt][3] + bb1, 0.0f)));
            *reinterpret_cast<float2*>(&sA[r0 * ROWP + col])       = v0;
            *reinterpret_cast<float2*>(&sA[(r0 + 8) * ROWP + col]) = v1;
        }
    }
    __syncthreads();

    // ================= scores GEMM: [64 x 8] per warp =================
    float sc[4][4] = {};
    const int p0 = w * 8;

    uint32_t af[2][4][4];
    uint32_t kf[2][2];
    {
#pragma unroll
        for (int mt = 0; mt < 4; mt++) {
            const float* pA = &sA[(mt * 16 + gid) * ROWP + tig];
            af[0][mt][0] = __float_as_uint(pA[0]);
            af[0][mt][1] = __float_as_uint(pA[8 * ROWP]);
            af[0][mt][2] = __float_as_uint(pA[4]);
            af[0][mt][3] = __float_as_uint(pA[8 * ROWP + 4]);
        }
        const float* pK = &sKey[(p0 + gid) * ROWP + tig];
        kf[0][0] = __float_as_uint(pK[0]);
        kf[0][1] = __float_as_uint(pK[4]);
    }

#pragma unroll 4
    for (int kt = 0; kt < 32; kt++) {
        const int cur = kt & 1, nxt = cur ^ 1;
        if (kt < 31) {
            const int k1 = (kt + 1) * 8;
#pragma unroll
            for (int mt = 0; mt < 4; mt++) {
                const float* pA = &sA[(mt * 16 + gid) * ROWP + k1 + tig];
                af[nxt][mt][0] = __float_as_uint(pA[0]);
                af[nxt][mt][1] = __float_as_uint(pA[8 * ROWP]);
                af[nxt][mt][2] = __float_as_uint(pA[4]);
                af[nxt][mt][3] = __float_as_uint(pA[8 * ROWP + 4]);
            }
            const float* pK = &sKey[(p0 + gid) * ROWP + k1 + tig];
            kf[nxt][0] = __float_as_uint(pK[0]);
            kf[nxt][1] = __float_as_uint(pK[4]);
        }
#pragma unroll
        for (int mt = 0; mt < 4; mt++)
            mma8(sc[mt], af[cur][mt], kf[cur][0], kf[cur][1]);
    }

    // ---- epilogue: relu6 -> g_scores[b][t][p] ----
    {
        float* gs = g_scores + ((size_t)b * TSTEP + t0) * NPAT;
        const int p = p0 + 2 * tig;
#pragma unroll
        for (int mt = 0; mt < 4; mt++) {
            const int r0 = mt * 16 + gid;
            float2 u0 = make_float2(fminf(fmaxf(sc[mt][0], 0.0f), 6.0f),
                                    fminf(fmaxf(sc[mt][1], 0.0f), 6.0f));
            float2 u1 = make_float2(fminf(fmaxf(sc[mt][2], 0.0f), 6.0f),
                                    fminf(fmaxf(sc[mt][3], 0.0f), 6.0f));
            *reinterpret_cast<float2*>(&gs[r0 * NPAT + p])       = u0;
            *reinterpret_cast<float2*>(&gs[(r0 + 8) * NPAT + p]) = u1;
        }
    }
}

// ---------------------------------------------------------------------------
// Kernel 2: producer/consumer split.
// Warp 0: softmax-EMA recurrence only (depth-8 score prefetch), e + 1/sum
// into double-buffered ring. Warps 1-3: GEMV + relu(sig - x) on chunk c-1.
// ---------------------------------------------------------------------------
__global__ __launch_bounds__(128)
void scan_signal_kernel(const float* __restrict__ avg_scores,
                        const float* __restrict__ shapes,
                        const float* __restrict__ x,
                        float* __restrict__ out)
{
    const int b    = blockIdx.x;
    const int tid  = threadIdx.x;
    const int w    = tid >> 5;
    const int lane = tid & 31;

    __shared__ __align__(16) float ring[2][CCH][NPAT];   // 32 KB
    __shared__ float s_inv[2][CCH];                      // 512 B
    __shared__ __align__(16) float s_x[CCH * WINW];      // 16 KB

    const float* srow = g_scores + (size_t)b * TSTEP * NPAT;
    const float* xrow = x   + (size_t)b * LSEQ;
    float*       orow = out + (size_t)b * LSEQ;
    const float invP = 1.0f / (float)NPAT;

    // ---- consumer-only: shapes in registers, packed pattern pairs ----
    uint64_t shp0[NPAT / 2], shp1[NPAT / 2];
    if (w > 0) {
#pragma unroll
        for (int i = 0; i < NPAT / 2; i++) {
            float a0 = shapes[(2 * i) * WINW + lane];
            float a1 = shapes[(2 * i + 1) * WINW + lane];
            asm("mov.b64 %0, {%1, %2};" : "=l"(shp0[i]) : "f"(a0), "f"(a1));
            float c0 = shapes[(2 * i) * WINW + lane + 32];
            float c1 = shapes[(2 * i + 1) * WINW + lane + 32];
            asm("mov.b64 %0, {%1, %2};" : "=l"(shp1[i]) : "f"(c0), "f"(c1));
        }
    }

    // ---- producer-only state ----
    float avg0 = 0.0f, avg1 = 0.0f;
    float pf0[8], pf1[8];
    if (w == 0) {
        avg0 = avg_scores[b * NPAT + lane];
        avg1 = avg_scores[b * NPAT + lane + 32];
#pragma unroll
        for (int j = 0; j < 8; j++) {
            pf0[j] = srow[j * NPAT + lane];
            pf1[j] = srow[j * NPAT + lane + 32];
        }
    }

    for (int c = 0; c <= NCH; c++) {
        if (w == 0) {
            if (c < NCH) {
                float* buf = &ring[c & 1][0][0];
                float* biv = s_inv[c & 1];
#pragma unroll 1
                for (int u = 0; u < CCH; u += 8) {
#pragma unroll
                    for (int j = 0; j < 8; j++) {
                        const int tt = u + j;
                        const int t  = c * CCH + tt;
                        const float s0 = pf0[j];
                        const float s1 = pf1[j];
                        const int tn = t + 8;
                        if (tn < TSTEP) {
                            pf0[j] = srow[tn * NPAT + lane];
                            pf1[j] = srow[tn * NPAT + lane + 32];
                        }
                        const float e0 = __expf(s0 - avg0);
                        const float e1 = __expf(s1 - avg1);
                        buf[tt * NPAT + lane]      = e0;
                        buf[tt * NPAT + lane + 32] = e1;
                        float sum = e0 + e1;
#pragma unroll
                        for (int o = 16; o > 0; o >>= 1)
                            sum += __shfl_xor_sync(0xFFFFFFFFu, sum, o);
                        const float inv = __fdividef(1.0f, sum);
                        if (lane == 0) biv[tt] = inv;
                        const float a0p = avg0 - invP;   // off critical path
                        const float a1p = avg1 - invP;
                        avg0 = fmaf(e0, inv, a0p);
                        avg1 = fmaf(e1, inv, a1p);
                    }
                }
            }
        } else {
            if (c > 0) {
                const int cc = c - 1;
                const float* buf = &ring[cc & 1][0][0];
                const float* biv = s_inv[cc & 1];

                // stage this chunk's x into smem (96 threads, float4)
                const float4* xc = reinterpret_cast<const float4*>(
                                       xrow + (size_t)cc * CCH * WINW);
                float4* sx4 = reinterpret_cast<float4*>(s_x);
                for (int i = tid - 32; i < CCH * WINW / 4; i += 96)
                    sx4[i] = xc[i];
                asm volatile("bar.sync 1, 96;" ::: "memory");

                for (int tt = w - 1; tt < CCH; tt += 3) {
                    const uint64_t* ep =
                        reinterpret_cast<const uint64_t*>(buf + tt * NPAT);
                    const float inv = biv[tt];
                    uint64_t acc0 = 0ull, acc1 = 0ull;
#pragma unroll
                    for (int i = 0; i < NPAT / 2; i++) {
                        const uint64_t ev = ep[i];
                        asm("fma.rn.f32x2 %0, %1, %2, %0;"
                            : "+l"(acc0) : "l"(ev), "l"(shp0[i]));
                        asm("fma.rn.f32x2 %0, %1, %2, %0;"
                            : "+l"(acc1) : "l"(ev), "l"(shp1[i]));
                    }
                    float l0, h0, l1, h1;
                    asm("mov.b64 {%0, %1}, %2;" : "=f"(l0), "=f"(h0) : "l"(acc0));
                    asm("mov.b64 {%0, %1}, %2;" : "=f"(l1), "=f"(h1) : "l"(acc1));
                    const float sig0 = (l0 + h0) * inv;
                    const float sig1 = (l1 + h1) * inv;

                    const float xa = s_x[tt * WINW + lane];
                    const float xb = s_x[tt * WINW + lane + 32];
                    const int o0 = (cc * CCH + tt) * WINW + lane;
                    orow[o0]      = fmaxf(sig0 - xa, 0.0f);
                    orow[o0 + 32] = fmaxf(sig1 - xb, 0.0f);
                }
            }
        }
        __syncthreads();
    }
}

// ---------------------------------------------------------------------------
extern "C" void kernel_launch(void* const* d_in, const int* in_sizes, int n_in,
                              void* d_out, int out_size)
{
    const float* x          = (const float*)d_in[0];
    const float* avg_scores = (const float*)d_in[1];
    const float* conv_w     = (const float*)d_in[2];
    const float* conv_b     = (const float*)d_in[3];
    const float* keys       = (const float*)d_in[4];
    const float* shapes     = (const float*)d_in[5];
    float* out = (float*)d_out;

    cudaFuncSetAttribute(conv_scores_mma,
                         cudaFuncAttributeMaxDynamicSharedMemorySize,
                         SMEM_BYTES);

    dim3 grid1(BSZ, TSTEP / TT);   // 256 x 16
    conv_scores_mma<<<grid1, 256, SMEM_BYTES>>>(x, conv_w, conv_b, keys);

    scan_signal_kernel<<<BSZ, 128>>>(avg_scores, shapes, x, out);
}

// round 9
// speedup vs baseline: 4.0773x; 1.2465x over previous
#include <cuda_runtime.h>
#include <cuda_bf16.h>
#include <cstdint>

// Problem constants
#define BSZ   256
#define LSEQ  65536
#define HIST  256
#define WINW  64
#define DIMC  256
#define NPAT  64
#define TSTEP 1024

// Kernel-1 tiling
#define TT    64                 // t rows per block
#define XWIN  ((TT-1)*WINW + HIST)   // 4288 compact x floats
#define ROWP  260                // souts padded row stride

// smem layout (floats) for kernel 1
#define OFF_SX   0                      // 4352 (4288 rounded up)
#define OFF_OUT  4352                   // souts: 64 x 260
#define OFF_BIAS (OFF_OUT + 64*ROWP)    // 21	-> 20992
#define K1_SMEM_FLOATS (OFF_BIAS + 256)
#define K1_SMEM_BYTES  (K1_SMEM_FLOATS * 4)   // ~85 KB

// Kernel-2 chunking
#define SCCH  32
#define SNCH  (TSTEP / SCCH)            // 32

// Scratch
__device__ float g_scores[BSZ * TSTEP * NPAT];   // 64 MiB
__device__ float g_wT[HIST * DIMC];              // W^T [k][n], tf32-rounded
__device__ float g_keysR[DIMC * NPAT];           // keys [d][p], tf32-rounded

// ---------------------------------------------------------------------------
__device__ __forceinline__ uint32_t f2tf32(float f) {
    uint32_t r;
    asm("cvt.rna.tf32.f32 %0, %1;" : "=r"(r) : "f"(f));
    return r;
}
__device__ __forceinline__ float tf32r(float f) {
    return __uint_as_float(f2tf32(f));
}

// D += A(16x8, tf32, row) * B(8x8, tf32, col), fp32 accum
__device__ __forceinline__ void mma8(float c[4], const uint32_t a[4],
                                     uint32_t b0, uint32_t b1) {
    asm volatile(
        "mma.sync.aligned.m16n8k8.row.col.f32.tf32.tf32.f32 "
        "{%0,%1,%2,%3}, {%4,%5,%6,%7}, {%8,%9}, {%0,%1,%2,%3};\n"
        : "+f"(c[0]), "+f"(c[1]), "+f"(c[2]), "+f"(c[3])
        : "r"(a[0]), "r"(a[1]), "r"(a[2]), "r"(a[3]), "r"(b0), "r"(b1));
}

// ---------------------------------------------------------------------------
// Prep: W -> [k][n] transposed + tf32-rounded; keys tf32-rounded (layout kept)
// ---------------------------------------------------------------------------
__global__ void prep_kernel(const float* __restrict__ conv_w,
                            const float* __restrict__ keys)
{
    const int i = blockIdx.x * 256 + threadIdx.x;   // 0..65535
    const int k = i >> 8, n = i & 255;
    g_wT[i] = tf32r(conv_w[n * HIST + k]);
    if (i < DIMC * NPAT) g_keysR[i] = tf32r(keys[i]);
}

// ---------------------------------------------------------------------------
// Kernel 1: conv-as-GEMM (tf32 MMA) + relu + scores-GEMM + relu6.
// 512 threads (16 warps). Conv: warp w owns cols [16w,16w+16), all 64 t.
// x kept COMPACT in smem with XOR swizzle (conflict-free strided frags).
// Scores: warps 0-7, 8 p-cols each; keys/W streamed from prepped globals.
// ---------------------------------------------------------------------------
__global__ __launch_bounds__(512, 1)
void conv_scores_mma(const float* __restrict__ x,
                     const float* __restrict__ conv_b)
{
    extern __shared__ float sm[];
    float* sx    = sm + OFF_SX;     // compact x windows, tf32, swizzled
    float* souts = sm + OFF_OUT;    // conv output [64][260]
    float* sBias = sm + OFF_BIAS;

    const int b    = blockIdx.x;
    const int t0   = blockIdx.y * TT;
    const int tid  = threadIdx.x;
    const int w    = tid >> 5;
    const int lane = tid & 31;
    const int gid  = lane >> 2;     // 0..7
    const int tig  = lane & 3;      // 0..3

    // ---- stage compact x (swizzled, tf32-rounded, zero left pad) ----
    {
        const float* xr = x + (size_t)b * LSEQ;
        const int base = t0 * WINW - (HIST - 1);
        for (int i = tid; i < XWIN; i += 512) {
            const int pos = base + i;
            const float v = (pos >= 0) ? xr[pos] : 0.0f;
            const int ph = i ^ (((i >> 6) & 7) << 2);
            sx[ph] = tf32r(v);
        }
    }
    if (tid < 256) sBias[tid] = conv_b[tid];
    __syncthreads();

    // ================= conv GEMM: C[64 x 16] per warp =================
    float acc[4][2][4] = {};
    const int n0w = w * 16;

    uint32_t aw[2][4][4];
    float    wb[2][2][2];

    // fragment loaders
    auto loadA = [&](int kt, uint32_t a[4][4]) {
        const int k0 = kt * 8;
        const int v  = (gid + (k0 >> 6)) & 7;
        const int c0 = (k0 + tig) ^ (v << 2);
        const int c1 = (k0 + tig + 4) ^ (v << 2);
        const float* basep = sx + gid * 64;
#pragma unroll
        for (int mt = 0; mt < 4; mt++) {
            a[mt][0] = __float_as_uint(basep[mt * 1024 + c0]);
            a[mt][1] = __float_as_uint(basep[mt * 1024 + 512 + c0]);
            a[mt][2] = __float_as_uint(basep[mt * 1024 + c1]);
            a[mt][3] = __float_as_uint(basep[mt * 1024 + 512 + c1]);
        }
    };
    auto loadB = [&](int kt, float wb_[2][2]) {
        const float* pb = g_wT + (size_t)(kt * 8 + tig) * 256 + n0w + gid;
        wb_[0][0] = pb[0];
        wb_[0][1] = pb[4 * 256];
        wb_[1][0] = pb[8];
        wb_[1][1] = pb[4 * 256 + 8];
    };

    loadA(0, aw[0]);
    loadB(0, wb[0]);

#pragma unroll 4
    for (int kt = 0; kt < 32; kt++) {
        const int cur = kt & 1, nxt = cur ^ 1;
        if (kt < 31) {
            loadB(kt + 1, wb[nxt]);
            loadA(kt + 1, aw[nxt]);
        }
#pragma unroll
        for (int nt = 0; nt < 2; nt++) {
            const uint32_t b0 = __float_as_uint(wb[cur][nt][0]);
            const uint32_t b1 = __float_as_uint(wb[cur][nt][1]);
#pragma unroll
            for (int mt = 0; mt < 4; mt++)
                mma8(acc[mt][nt], aw[cur][mt], b0, b1);
        }
    }

    // ---- epilogue: bias + relu, tf32-round -> souts ----
#pragma unroll
    for (int mt = 0; mt < 4; mt++) {
#pragma unroll
        for (int nt = 0; nt < 2; nt++) {
            const int col = n0w + nt * 8 + 2 * tig;
            const float bb0 = sBias[col], bb1 = sBias[col + 1];
            const int r0 = mt * 16 + gid;
            float2 v0, v1;
            v0.x = tf32r(fmaxf(acc[mt][nt][0] + bb0, 0.0f));
            v0.y = tf32r(fmaxf(acc[mt][nt][1] + bb1, 0.0f));
            v1.x = tf32r(fmaxf(acc[mt][nt][2] + bb0, 0.0f));
            v1.y = tf32r(fmaxf(acc[mt][nt][3] + bb1, 0.0f));
            *reinterpret_cast<float2*>(&souts[r0 * ROWP + col])       = v0;
            *reinterpret_cast<float2*>(&souts[(r0 + 8) * ROWP + col]) = v1;
        }
    }
    __syncthreads();

    // ================= scores GEMM: [64 x 8] per warp, warps 0-7 ==========
    if (w < 8) {
        float sc[4][4] = {};
        const int p0 = w * 8;

        uint32_t af[2][4][4];
        uint32_t kf[2][2];

        auto loadA2 = [&](int kt, uint32_t a[4][4]) {
            const int k0 = kt * 8;
#pragma unroll
            for (int mt = 0; mt < 4; mt++) {
                const float* pA = &souts[(mt * 16 + gid) * ROWP + k0 + tig];
                a[mt][0] = __float_as_uint(pA[0]);
                a[mt][1] = __float_as_uint(pA[8 * ROWP]);
                a[mt][2] = __float_as_uint(pA[4]);
                a[mt][3] = __float_as_uint(pA[8 * ROWP + 4]);
            }
        };
        auto loadK = [&](int kt, uint32_t kf_[2]) {
            const float* pk = g_keysR + (size_t)(kt * 8 + tig) * 64 + p0 + gid;
            kf_[0] = __float_as_uint(pk[0]);
            kf_[1] = __float_as_uint(pk[4 * 64]);
        };

        loadA2(0, af[0]);
        loadK(0, kf[0]);

#pragma unroll 4
        for (int kt = 0; kt < 32; kt++) {
            const int cur = kt & 1, nxt = cur ^ 1;
            if (kt < 31) {
                loadK(kt + 1, kf[nxt]);
                loadA2(kt + 1, af[nxt]);
            }
#pragma unroll
            for (int mt = 0; mt < 4; mt++)
                mma8(sc[mt], af[cur][mt], kf[cur][0], kf[cur][1]);
        }

        // relu6 -> g_scores[b][t][p]
        float* gs = g_scores + ((size_t)b * TSTEP + t0) * NPAT;
        const int p = p0 + 2 * tig;
#pragma unroll
        for (int mt = 0; mt < 4; mt++) {
            const int r0 = mt * 16 + gid;
            float2 u0 = make_float2(fminf(fmaxf(sc[mt][0], 0.0f), 6.0f),
                                    fminf(fmaxf(sc[mt][1], 0.0f), 6.0f));
            float2 u1 = make_float2(fminf(fmaxf(sc[mt][2], 0.0f), 6.0f),
                                    fminf(fmaxf(sc[mt][3], 0.0f), 6.0f));
            *reinterpret_cast<float2*>(&gs[r0 * NPAT + p])       = u0;
            *reinterpret_cast<float2*>(&gs[(r0 + 8) * NPAT + p]) = u1;
        }
    }
}

// ---------------------------------------------------------------------------
// Kernel 2: 2 batches per block (grid 128 -> one clean wave).
// Warps 0/1: producers (softmax-EMA chain, depth-8 prefetch) on SMSP0/1.
// Warps 2-4 / 5-7: consumers (x staging + GEMV + relu(sig-x)) per batch.
// ---------------------------------------------------------------------------
__global__ __launch_bounds__(256)
void scan_signal_kernel(const float* __restrict__ avg_scores,
                        const float* __restrict__ shapes,
                        const float* __restrict__ x,
                        float* __restrict__ out)
{
    extern __shared__ float ds[];
    float* ring = ds;              // [2 batch][2 buf][SCCH][NPAT] = 8192 f
    float* rinv = ds + 8192;       // [2][2][SCCH] = 128 f
    float* sxb  = ds + 8320;       // [2][SCCH*WINW] = 4096 f

    const int tid  = threadIdx.x;
    const int w    = tid >> 5;
    const int lane = tid & 31;
    const float invP = 1.0f / (float)NPAT;

    // ---- producer state (w<2) ----
    float avg0 = 0.0f, avg1 = 0.0f;
    float pf0[8], pf1[8];
    const float* srow = nullptr;
    if (w < 2) {
        const int b = blockIdx.x * 2 + w;
        srow = g_scores + (size_t)b * TSTEP * NPAT;
        avg0 = avg_scores[b * NPAT + lane];
        avg1 = avg_scores[b * NPAT + lane + 32];
#pragma unroll
        for (int j = 0; j < 8; j++) {
            pf0[j] = srow[j * NPAT + lane];
            pf1[j] = srow[j * NPAT + lane + 32];
        }
    }

    // ---- consumer state (w>=2) ----
    uint64_t shp0[NPAT / 2], shp1[NPAT / 2];
    int g = 0, cw = 0, bc = 0;
    if (w >= 2) {
        g  = (w - 2) / 3;            // batch group 0/1
        cw = (w - 2) - 3 * g;        // 0..2 within group
        bc = blockIdx.x * 2 + g;
#pragma unroll
        for (int i = 0; i < NPAT / 2; i++) {
            float a0 = shapes[(2 * i) * WINW + lane];
            float a1 = shapes[(2 * i + 1) * WINW + lane];
            asm("mov.b64 %0, {%1, %2};" : "=l"(shp0[i]) : "f"(a0), "f"(a1));
            float c0 = shapes[(2 * i) * WINW + lane + 32];
            float c1 = shapes[(2 * i + 1) * WINW + lane + 32];
            asm("mov.b64 %0, {%1, %2};" : "=l"(shp1[i]) : "f"(c0), "f"(c1));
        }
    }

    for (int c = 0; c <= SNCH; c++) {
        if (w < 2) {
            if (c < SNCH) {
                float* buf = ring + (size_t)(w * 2 + (c & 1)) * SCCH * NPAT;
                float* biv = rinv + (w * 2 + (c & 1)) * SCCH;
#pragma unroll 1
                for (int u = 0; u < SCCH; u += 8) {
#pragma unroll
                    for (int j = 0; j < 8; j++) {
                        const int tt = u + j;
                        const int t  = c * SCCH + tt;
                        const float s0 = pf0[j];
                        const float s1 = pf1[j];
                        const int tn = t + 8;
                        if (tn < TSTEP) {
                            pf0[j] = srow[tn * NPAT + lane];
                            pf1[j] = srow[tn * NPAT + lane + 32];
                        }
                        const float e0 = __expf(s0 - avg0);
                        const float e1 = __expf(s1 - avg1);
                        buf[tt * NPAT + lane]      = e0;
                        buf[tt * NPAT + lane + 32] = e1;
                        float sum = e0 + e1;
#pragma unroll
                        for (int o = 16; o > 0; o >>= 1)
                            sum += __shfl_xor_sync(0xFFFFFFFFu, sum, o);
                        const float inv = __fdividef(1.0f, sum);
                        if (lane == 0) biv[tt] = inv;
                        const float a0p = avg0 - invP;
                        const float a1p = avg1 - invP;
                        avg0 = fmaf(e0, inv, a0p);
                        avg1 = fmaf(e1, inv, a1p);
                    }
                }
            }
        } else {
            if (c > 0) {
                const int cc = c - 1;
                const float* buf = ring + (size_t)(g * 2 + (cc & 1)) * SCCH * NPAT;
                const float* biv = rinv + (g * 2 + (cc & 1)) * SCCH;
                float* sx = sxb + g * (SCCH * WINW);

                // stage this chunk's x (96 threads per group, float4)
                const float4* xc = reinterpret_cast<const float4*>(
                    x + (size_t)bc * LSEQ + (size_t)cc * SCCH * WINW);
                float4* sx4 = reinterpret_cast<float4*>(sx);
                for (int i = cw * 32 + lane; i < SCCH * WINW / 4; i += 96)
                    sx4[i] = xc[i];
                if (g == 0) asm volatile("bar.sync 1, 96;" ::: "memory");
                else        asm volatile("bar.sync 2, 96;" ::: "memory");

                float* orow = out + (size_t)bc * LSEQ;
                for (int tt = cw; tt < SCCH; tt += 3) {
                    const uint64_t* ep =
                        reinterpret_cast<const uint64_t*>(buf + tt * NPAT);
                    const float inv = biv[tt];
                    uint64_t acc0 = 0ull, acc1 = 0ull;
#pragma unroll
                    for (int i = 0; i < NPAT / 2; i++) {
                        const uint64_t ev = ep[i];
                        asm("fma.rn.f32x2 %0, %1, %2, %0;"
                            : "+l"(acc0) : "l"(ev), "l"(shp0[i]));
                        asm("fma.rn.f32x2 %0, %1, %2, %0;"
                            : "+l"(acc1) : "l"(ev), "l"(shp1[i]));
                    }
                    float l0, h0, l1, h1;
                    asm("mov.b64 {%0, %1}, %2;" : "=f"(l0), "=f"(h0) : "l"(acc0));
                    asm("mov.b64 {%0, %1}, %2;" : "=f"(l1), "=f"(h1) : "l"(acc1));
                    const float sig0 = (l0 + h0) * inv;
                    const float sig1 = (l1 + h1) * inv;

                    const float xa = sx[tt * WINW + lane];
                    const float xb = sx[tt * WINW + lane + 32];
                    const int o0 = (cc * SCCH + tt) * WINW + lane;
                    orow[o0]      = fmaxf(sig0 - xa, 0.0f);
                    orow[o0 + 32] = fmaxf(sig1 - xb, 0.0f);
                }
            }
        }
        __syncthreads();
    }
}

// ---------------------------------------------------------------------------
extern "C" void kernel_launch(void* const* d_in, const int* in_sizes, int n_in,
                              void* d_out, int out_size)
{
    const float* x          = (const float*)d_in[0];
    const float* avg_scores = (const float*)d_in[1];
    const float* conv_w     = (const float*)d_in[2];
    const float* conv_b     = (const float*)d_in[3];
    const float* keys       = (const float*)d_in[4];
    const float* shapes     = (const float*)d_in[5];
    float* out = (float*)d_out;

    cudaFuncSetAttribute(conv_scores_mma,
                         cudaFuncAttributeMaxDynamicSharedMemorySize,
                         K1_SMEM_BYTES);
    static const int scan_smem = (8192 + 128 + 4096) * 4;   // ~48.7 KB
    cudaFuncSetAttribute(scan_signal_kernel,
                         cudaFuncAttributeMaxDynamicSharedMemorySize,
                         scan_smem);

    prep_kernel<<<256, 256>>>(conv_w, keys);

    dim3 grid1(BSZ, TSTEP / TT);   // 256 x 16
    conv_scores_mma<<<grid1, 512, K1_SMEM_BYTES>>>(x, conv_b);

    scan_signal_kernel<<<BSZ / 2, 256, scan_smem>>>(avg_scores, shapes, x, out);
}

// round 11
// speedup vs baseline: 5.7202x; 1.4029x over previous
#include <cuda_runtime.h>
#include <cuda_bf16.h>
#include <cstdint>

// Problem constants
#define BSZ   256
#define LSEQ  65536
#define HIST  256
#define WINW  64
#define DIMC  256
#define NPAT  64
#define TSTEP 1024

// Kernel-1 tiling
#define TT    64                     // t rows per block
#define XWIN  ((TT-1)*WINW + HIST)   // 4288 x elements per block
#define XWP   (XWIN/2)               // 2144 bf16x2 pairs
#define SOUTP 132                    // souts row stride (uints) -> bank = lane

// smem layout (uints) for kernel 1
#define OFF_SX    0                      // 2176 (2144 padded)
#define OFF_OUT   2176                   // souts: 64 x 132 bf16x2
#define OFF_BIAS  (OFF_OUT + 64*SOUTP)   // 10624 (floats)
#define K1_SMEM_UINTS (OFF_BIAS + 256)   // 10880
#define K1_SMEM_BYTES (K1_SMEM_UINTS * 4)

// Kernel-2 chunking
#define SCCH  32
#define SNCH  (TSTEP / SCCH)            // 32

// Scratch
__device__ float    g_scores[BSZ * TSTEP * NPAT];   // 64 MiB
__device__ uint32_t g_wP[(HIST/2) * DIMC];          // W^T bf16x2: [k2][n]
__device__ uint32_t g_keysP[(DIMC/2) * NPAT];       // keys bf16x2: [d2][p]

// ---------------------------------------------------------------------------
__device__ __forceinline__ uint32_t pack_bf16(float lo, float hi) {
    uint32_t r;
    asm("cvt.rn.bf16x2.f32 %0, %1, %2;" : "=r"(r) : "f"(hi), "f"(lo));
    return r;
}

// D += A(16x16 bf16, row) * B(16x8 bf16, col), fp32 accum
__device__ __forceinline__ void mma16(float c[4], const uint32_t a[4],
                                      uint32_t b0, uint32_t b1) {
    asm volatile(
        "mma.sync.aligned.m16n8k16.row.col.f32.bf16.bf16.f32 "
        "{%0,%1,%2,%3}, {%4,%5,%6,%7}, {%8,%9}, {%0,%1,%2,%3};\n"
        : "+f"(c[0]), "+f"(c[1]), "+f"(c[2]), "+f"(c[3])
        : "r"(a[0]), "r"(a[1]), "r"(a[2]), "r"(a[3]), "r"(b0), "r"(b1));
}

// ---------------------------------------------------------------------------
// Prep: W -> [k2][n] bf16x2 (pairs along k); keys -> [d2][p] bf16x2 (pairs
// along d). Both become 32B-coalesced B-fragment loads in kernel 1.
// ---------------------------------------------------------------------------
__global__ void prep_kernel(const float* __restrict__ conv_w,
                            const float* __restrict__ keys)
{
    const int i = blockIdx.x * 256 + threadIdx.x;   // 0..32767
    const int k2 = i >> 8, n = i & 255;
    g_wP[i] = pack_bf16(conv_w[n * HIST + 2 * k2],
                        conv_w[n * HIST + 2 * k2 + 1]);
    if (i < (DIMC / 2) * NPAT) {
        const int d2 = i >> 6, p = i & 63;
        g_keysP[i] = pack_bf16(keys[(2 * d2) * NPAT + p],
                               keys[(2 * d2 + 1) * NPAT + p]);
    }
}

// ---------------------------------------------------------------------------
// Kernel 1: conv-as-GEMM (bf16 m16n8k16) + relu + scores-GEMM + relu6.
// 512 threads (16 warps). Conv: warp w owns cols [16w,16w+16), all 64 t;
// x kept compact as bf16x2 pairs with XOR swizzle (conflict-free frags).
// Scores: warp = (mt = w&3) x (p-group = w>>2, 16 p each).
// ---------------------------------------------------------------------------
__global__ __launch_bounds__(512, 1)
void conv_scores_mma(const float* __restrict__ x,
                     const float* __restrict__ conv_b)
{
    extern __shared__ uint32_t smu[];
    uint32_t* sxp   = smu + OFF_SX;    // compact x, bf16x2, swizzled
    uint32_t* soutp = smu + OFF_OUT;   // conv out, bf16x2 [64][132]
    float*    sBias = (float*)(smu + OFF_BIAS);

    const int b    = blockIdx.x;
    const int t0   = blockIdx.y * TT;
    const int tid  = threadIdx.x;
    const int w    = tid >> 5;
    const int lane = tid & 31;
    const int gid  = lane >> 2;     // 0..7
    const int tig  = lane & 3;      // 0..3

    // ---- stage compact x as bf16x2 pairs (swizzled, zero left pad) ----
    {
        const float* xr = x + (size_t)b * LSEQ;
        const int base = t0 * WINW - (HIST - 1);
        for (int i = tid; i < XWP; i += 512) {
            const int p0 = base + 2 * i;
            const float v0 = (p0     >= 0) ? xr[p0]     : 0.0f;
            const float v1 = (p0 + 1 >= 0) ? xr[p0 + 1] : 0.0f;
            const int ph = i ^ (((i >> 5) & 7) << 2);
            sxp[ph] = pack_bf16(v0, v1);
        }
    }
    if (tid < 256) sBias[tid] = conv_b[tid];
    __syncthreads();

    // ================= conv GEMM: C[64 x 16] per warp =================
    float acc[4][2][4] = {};
    const int n0w = w * 16;

    uint32_t aw[2][4][4];
    uint32_t wb[2][2][2];

    auto loadA = [&](int kt, uint32_t a[4][4]) {
        const int j0 = kt * 8;
        const int v  = (gid + (kt >> 2)) & 7;      // (j0>>5) contribution
        const int c0 = (j0 + tig)     ^ (v << 2);
        const int c1 = (j0 + tig + 4) ^ (v << 2);
        const uint32_t* bp = sxp + gid * 32;
#pragma unroll
        for (int mt = 0; mt < 4; mt++) {
            a[mt][0] = bp[mt * 512 + c0];
            a[mt][1] = bp[mt * 512 + 256 + c0];
            a[mt][2] = bp[mt * 512 + c1];
            a[mt][3] = bp[mt * 512 + 256 + c1];
        }
    };
    auto loadB = [&](int kt, uint32_t wb_[2][2]) {
        const uint32_t* pb = g_wP + (size_t)(kt * 8 + tig) * 256 + n0w + gid;
        wb_[0][0] = pb[0];
        wb_[0][1] = pb[4 * 256];
        wb_[1][0] = pb[8];
        wb_[1][1] = pb[4 * 256 + 8];
    };

    loadA(0, aw[0]);
    loadB(0, wb[0]);

#pragma unroll 4
    for (int kt = 0; kt < 16; kt++) {
        const int cur = kt & 1, nxt = cur ^ 1;
        if (kt < 15) {
            loadB(kt + 1, wb[nxt]);
            loadA(kt + 1, aw[nxt]);
        }
#pragma unroll
        for (int nt = 0; nt < 2; nt++) {
#pragma unroll
            for (int mt = 0; mt < 4; mt++)
                mma16(acc[mt][nt], aw[cur][mt], wb[cur][nt][0], wb[cur][nt][1]);
        }
    }

    // ---- epilogue: bias + relu -> bf16x2 pairs (along d) in soutp ----
#pragma unroll
    for (int mt = 0; mt < 4; mt++) {
#pragma unroll
        for (int nt = 0; nt < 2; nt++) {
            const int col = n0w + nt * 8 + 2 * tig;
            const float bb0 = sBias[col], bb1 = sBias[col + 1];
            const int jd = (n0w >> 1) + nt * 4 + tig;
            const int r0 = mt * 16 + gid;
            soutp[r0 * SOUTP + jd] =
                pack_bf16(fmaxf(acc[mt][nt][0] + bb0, 0.0f),
                          fmaxf(acc[mt][nt][1] + bb1, 0.0f));
            soutp[(r0 + 8) * SOUTP + jd] =
                pack_bf16(fmaxf(acc[mt][nt][2] + bb0, 0.0f),
                          fmaxf(acc[mt][nt][3] + bb1, 0.0f));
        }
    }
    __syncthreads();

    // ================= scores GEMM: warp = mt x 16-p group =================
    {
        const int mt = w & 3;          // t-tile (16 rows)
        const int pg = w >> 2;         // p-group (16 cols)
        float sc[2][4] = {};

        uint32_t af[2][4];
        uint32_t kf[2][2][2];

        auto loadA2 = [&](int kt, uint32_t a[4]) {
            const uint32_t* pA = soutp + (mt * 16 + gid) * SOUTP + kt * 8 + tig;
            a[0] = pA[0];
            a[1] = pA[8 * SOUTP];
            a[2] = pA[4];
            a[3] = pA[8 * SOUTP + 4];
        };
        auto loadK = [&](int kt, uint32_t kf_[2][2]) {
            const uint32_t* pk = g_keysP + (size_t)(kt * 8 + tig) * 64
                                 + pg * 16 + gid;
            kf_[0][0] = pk[0];
            kf_[0][1] = pk[4 * 64];
            kf_[1][0] = pk[8];
            kf_[1][1] = pk[4 * 64 + 8];
        };

        loadA2(0, af[0]);
        loadK(0, kf[0]);

#pragma unroll 4
        for (int kt = 0; kt < 16; kt++) {
            const int cur = kt & 1, nxt = cur ^ 1;
            if (kt < 15) {
                loadK(kt + 1, kf[nxt]);
                loadA2(kt + 1, af[nxt]);
            }
            mma16(sc[0], af[cur], kf[cur][0][0], kf[cur][0][1]);
            mma16(sc[1], af[cur], kf[cur][1][0], kf[cur][1][1]);
        }

        // relu6 -> g_scores[b][t][p]
        float* gs = g_scores + ((size_t)b * TSTEP + t0) * NPAT;
#pragma unroll
        for (int nt = 0; nt < 2; nt++) {
            const int p  = pg * 16 + nt * 8 + 2 * tig;
            const int r0 = mt * 16 + gid;
            float2 u0 = make_float2(fminf(fmaxf(sc[nt][0], 0.0f), 6.0f),
                                    fminf(fmaxf(sc[nt][1], 0.0f), 6.0f));
            float2 u1 = make_float2(fminf(fmaxf(sc[nt][2], 0.0f), 6.0f),
                                    fminf(fmaxf(sc[nt][3], 0.0f), 6.0f));
            *reinterpret_cast<float2*>(&gs[r0 * NPAT + p])       = u0;
            *reinterpret_cast<float2*>(&gs[(r0 + 8) * NPAT + p]) = u1;
        }
    }
}

// ---------------------------------------------------------------------------
// Kernel 2: 2 batches per block (grid 128 -> one clean wave).
// Warps 0/1: producers (softmax-EMA chain, depth-8 prefetch) on SMSP0/1.
// Warps 2-4 / 5-7: consumers (x staging + GEMV + relu(sig-x)) per batch.
// ---------------------------------------------------------------------------
__global__ __launch_bounds__(256)
void scan_signal_kernel(const float* __restrict__ avg_scores,
                        const float* __restrict__ shapes,
                        const float* __restrict__ x,
                        float* __restrict__ out)
{
    extern __shared__ float ds[];
    float* ring = ds;              // [2 batch][2 buf][SCCH][NPAT] = 8192 f
    float* rinv = ds + 8192;       // [2][2][SCCH] = 128 f
    float* sxb  = ds + 8320;       // [2][SCCH*WINW] = 4096 f

    const int tid  = threadIdx.x;
    const int w    = tid >> 5;
    const int lane = tid & 31;
    const float invP = 1.0f / (float)NPAT;

    // ---- producer state (w<2) ----
    float avg0 = 0.0f, avg1 = 0.0f;
    float pf0[8], pf1[8];
    const float* srow = nullptr;
    if (w < 2) {
        const int b = blockIdx.x * 2 + w;
        srow = g_scores + (size_t)b * TSTEP * NPAT;
        avg0 = avg_scores[b * NPAT + lane];
        avg1 = avg_scores[b * NPAT + lane + 32];
#pragma unroll
        for (int j = 0; j < 8; j++) {
            pf0[j] = srow[j * NPAT + lane];
            pf1[j] = srow[j * NPAT + lane + 32];
        }
    }

    // ---- consumer state (w>=2) ----
    uint64_t shp0[NPAT / 2], shp1[NPAT / 2];
    int g = 0, cw = 0, bc = 0;
    if (w >= 2) {
        g  = (w - 2) / 3;            // batch group 0/1
        cw = (w - 2) - 3 * g;        // 0..2 within group
        bc = blockIdx.x * 2 + g;
#pragma unroll
        for (int i = 0; i < NPAT / 2; i++) {
            float a0 = shapes[(2 * i) * WINW + lane];
            float a1 = shapes[(2 * i + 1) * WINW + lane];
            asm("mov.b64 %0, {%1, %2};" : "=l"(shp0[i]) : "f"(a0), "f"(a1));
            float c0 = shapes[(2 * i) * WINW + lane + 32];
            float c1 = shapes[(2 * i + 1) * WINW + lane + 32];
            asm("mov.b64 %0, {%1, %2};" : "=l"(shp1[i]) : "f"(c0), "f"(c1));
        }
    }

    for (int c = 0; c <= SNCH; c++) {
        if (w < 2) {
            if (c < SNCH) {
                float* buf = ring + (size_t)(w * 2 + (c & 1)) * SCCH * NPAT;
                float* biv = rinv + (w * 2 + (c & 1)) * SCCH;
#pragma unroll 1
                for (int u = 0; u < SCCH; u += 8) {
#pragma unroll
                    for (int j = 0; j < 8; j++) {
                        const int tt = u + j;
                        const int t  = c * SCCH + tt;
                        const float s0 = pf0[j];
                        const float s1 = pf1[j];
                        const int tn = t + 8;
                        if (tn < TSTEP) {
                            pf0[j] = srow[tn * NPAT + lane];
                            pf1[j] = srow[tn * NPAT + lane + 32];
                        }
                        const float e0 = __expf(s0 - avg0);
                        const float e1 = __expf(s1 - avg1);
                        buf[tt * NPAT + lane]      = e0;
                        buf[tt * NPAT + lane + 32] = e1;
                        float sum = e0 + e1;
#pragma unroll
                        for (int o = 16; o > 0; o >>= 1)
                            sum += __shfl_xor_sync(0xFFFFFFFFu, sum, o);
                        const float inv = __fdividef(1.0f, sum);
                        if (lane == 0) biv[tt] = inv;
                        const float a0p = avg0 - invP;
                        const float a1p = avg1 - invP;
                        avg0 = fmaf(e0, inv, a0p);
                        avg1 = fmaf(e1, inv, a1p);
                    }
                }
            }
        } else {
            if (c > 0) {
                const int cc = c - 1;
                const float* buf = ring + (size_t)(g * 2 + (cc & 1)) * SCCH * NPAT;
                const float* biv = rinv + (g * 2 + (cc & 1)) * SCCH;
                float* sx = sxb + g * (SCCH * WINW);

                // stage this chunk's x (96 threads per group, float4)
                const float4* xc = reinterpret_cast<const float4*>(
                    x + (size_t)bc * LSEQ + (size_t)cc * SCCH * WINW);
                float4* sx4 = reinterpret_cast<float4*>(sx);
                for (int i = cw * 32 + lane; i < SCCH * WINW / 4; i += 96)
                    sx4[i] = xc[i];
                if (g == 0) asm volatile("bar.sync 1, 96;" ::: "memory");
                else        asm volatile("bar.sync 2, 96;" ::: "memory");

                float* orow = out + (size_t)bc * LSEQ;
                for (int tt = cw; tt < SCCH; tt += 3) {
                    const uint64_t* ep =
                        reinterpret_cast<const uint64_t*>(buf + tt * NPAT);
                    const float inv = biv[tt];
                    uint64_t acc0 = 0ull, acc1 = 0ull;
#pragma unroll
                    for (int i = 0; i < NPAT / 2; i++) {
                        const uint64_t ev = ep[i];
                        asm("fma.rn.f32x2 %0, %1, %2, %0;"
                            : "+l"(acc0) : "l"(ev), "l"(shp0[i]));
                        asm("fma.rn.f32x2 %0, %1, %2, %0;"
                            : "+l"(acc1) : "l"(ev), "l"(shp1[i]));
                    }
                    float l0, h0, l1, h1;
                    asm("mov.b64 {%0, %1}, %2;" : "=f"(l0), "=f"(h0) : "l"(acc0));
                    asm("mov.b64 {%0, %1}, %2;" : "=f"(l1), "=f"(h1) : "l"(acc1));
                    const float sig0 = (l0 + h0) * inv;
                    const float sig1 = (l1 + h1) * inv;

                    const float xa = sx[tt * WINW + lane];
                    const float xb = sx[tt * WINW + lane + 32];
                    const int o0 = (cc * SCCH + tt) * WINW + lane;
                    orow[o0]      = fmaxf(sig0 - xa, 0.0f);
                    orow[o0 + 32] = fmaxf(sig1 - xb, 0.0f);
                }
            }
        }
        __syncthreads();
    }
}

// ---------------------------------------------------------------------------
extern "C" void kernel_launch(void* const* d_in, const int* in_sizes, int n_in,
                              void* d_out, int out_size)
{
    const float* x          = (const float*)d_in[0];
    const float* avg_scores = (const float*)d_in[1];
    const float* conv_w     = (const float*)d_in[2];
    const float* conv_b     = (const float*)d_in[3];
    const float* keys       = (const float*)d_in[4];
    const float* shapes     = (const float*)d_in[5];
    float* out = (float*)d_out;

    cudaFuncSetAttribute(conv_scores_mma,
                         cudaFuncAttributeMaxDynamicSharedMemorySize,
                         K1_SMEM_BYTES);
    static const int scan_smem = (8192 + 128 + 4096) * 4;   // ~48.7 KB
    cudaFuncSetAttribute(scan_signal_kernel,
                         cudaFuncAttributeMaxDynamicSharedMemorySize,
                         scan_smem);

    prep_kernel<<<128, 256>>>(conv_w, keys);

    dim3 grid1(BSZ, TSTEP / TT);   // 256 x 16
    conv_scores_mma<<<grid1, 512, K1_SMEM_BYTES>>>(x, conv_b);

    scan_signal_kernel<<<BSZ / 2, 256, scan_smem>>>(avg_scores, shapes, x, out);
}